// round 12
// baseline (speedup 1.0000x reference)
#include <cuda_runtime.h>
#include <math.h>
#include <stdint.h>

// Problem constants
constexpr int Bc  = 2;
constexpr int Sc  = 2048;
constexpr int Dc  = 1024;
constexpr int Hc  = 16;
constexpr int HDc = 64;
constexpr int Mc  = Bc * Sc;          // 4096 rows for projections

// ---------------------------------------------------------------------------
// Device scratch (allocations forbidden; use __device__ globals)
// ---------------------------------------------------------------------------
__device__ float g_q[(size_t)Bc * Sc * Dc];
__device__ float g_k[(size_t)Bc * Sc * Dc];
__device__ float g_v[(size_t)Bc * Sc * Dc];
__device__ float g_ctx[(size_t)Bc * Sc * Dc];
__device__ float g_xr[(size_t)Mc * Dc];         // rounded x
__device__ float g_wr[4][(size_t)Dc * Dc];      // rounded Wq, Wk, Wv, Wo

// ---------------------------------------------------------------------------
// Helpers
// ---------------------------------------------------------------------------
__device__ __forceinline__ uint32_t f2tf32(float f) {
    uint32_t u;
    asm("cvt.rna.tf32.f32 %0, %1;" : "=r"(u) : "f"(f));
    return u;
}
__device__ __forceinline__ float f2tf32f(float f) {
    return __uint_as_float(f2tf32(f));
}

// D += A(16x8, tf32) * B(8x8, tf32)   (m16n8k8, row.col)
__device__ __forceinline__ void mma_tf32(float* d, const uint32_t* a, const uint32_t* b) {
    asm volatile(
        "mma.sync.aligned.m16n8k8.row.col.f32.tf32.tf32.f32 "
        "{%0,%1,%2,%3}, {%4,%5,%6,%7}, {%8,%9}, {%0,%1,%2,%3};"
        : "+f"(d[0]), "+f"(d[1]), "+f"(d[2]), "+f"(d[3])
        : "r"(a[0]), "r"(a[1]), "r"(a[2]), "r"(a[3]), "r"(b[0]), "r"(b[1]));
}

__device__ __forceinline__ void cp16(uint32_t smem_dst, const void* gmem_src) {
    asm volatile("cp.async.cg.shared.global [%0], [%1], 16;"
                 :: "r"(smem_dst), "l"(gmem_src));
}
__device__ __forceinline__ void cp_commit() {
    asm volatile("cp.async.commit_group;");
}
template <int N>
__device__ __forceinline__ void cp_wait() {
    asm volatile("cp.async.wait_group %0;" :: "n"(N));
}

// ---------------------------------------------------------------------------
// One-shot RNA rounding of x and all four weight matrices.
// ---------------------------------------------------------------------------
__global__ __launch_bounds__(256) void round_inputs(
    const float* __restrict__ x,
    const float* __restrict__ Wq, const float* __restrict__ Wk,
    const float* __restrict__ Wv, const float* __restrict__ Wo)
{
    const size_t NX = (size_t)Mc * Dc / 4;
    const size_t NW = (size_t)Dc * Dc / 4;
    const size_t total = NX + 4 * NW;
    const size_t stride = (size_t)gridDim.x * blockDim.x;

    for (size_t i = (size_t)blockIdx.x * blockDim.x + threadIdx.x; i < total; i += stride) {
        const float4* src;
        float4* dst;
        if (i < NX) {
            src = (const float4*)x + i;
            dst = (float4*)g_xr + i;
        } else {
            const size_t j = i - NX;
            const int w = (int)(j / NW);
            const size_t o = j % NW;
            const float* ws = (w == 0) ? Wq : (w == 1) ? Wk : (w == 2) ? Wv : Wo;
            src = (const float4*)ws + o;
            dst = (float4*)g_wr[w] + o;
        }
        const float4 v = *src;
        *dst = make_float4(f2tf32f(v.x), f2tf32f(v.y), f2tf32f(v.z), f2tf32f(v.w));
    }
}

// ---------------------------------------------------------------------------
// tf32 GEMM v3 (NT), 3 problems via blockIdx.z, cp.async double-buffered.
// (unchanged from R11 — proven at 85.9us per 512-CTA launch)
// ---------------------------------------------------------------------------
constexpr int NKC     = Dc / 32;                 // 32 k-chunks
constexpr int A_FLTS  = 128 * 36;                // one A buffer (floats)
constexpr int B_FLTS  = 64 * 36;
constexpr int G_SMEM  = 2 * (A_FLTS + B_FLTS) * 4;   // 55296 B

__global__ __launch_bounds__(256, 3) void gemm3_cp(
    const float* __restrict__ A,
    const float* __restrict__ W0, const float* __restrict__ b0, float* __restrict__ C0,
    const float* __restrict__ W1, const float* __restrict__ b1, float* __restrict__ C1,
    const float* __restrict__ W2, const float* __restrict__ b2, float* __restrict__ C2,
    int roundOut)
{
    const int z = blockIdx.z;
    const float* B    = (z == 0) ? W0 : (z == 1) ? W1 : W2;
    const float* bias = (z == 0) ? b0 : (z == 1) ? b1 : b2;
    float*       C    = (z == 0) ? C0 : (z == 1) ? C1 : C2;

    extern __shared__ float sm[];
    float* AsBase = sm;
    float* BsBase = sm + 2 * A_FLTS;

    const int tid  = threadIdx.x;
    const int lane = tid & 31;
    const int warp = tid >> 5;
    const int wm   = warp >> 1;
    const int wn   = warp & 1;
    const int g    = lane >> 2;
    const int t    = lane & 3;
    const int bm   = blockIdx.y * 128;
    const int bn   = blockIdx.x * 64;

    float acc[2][4][4];
#pragma unroll
    for (int mt = 0; mt < 2; mt++)
#pragma unroll
        for (int nt = 0; nt < 4; nt++)
#pragma unroll
            for (int i = 0; i < 4; i++) acc[mt][nt][i] = 0.f;

    auto copy_chunk = [&](int kc, int buf) {
        const int k0 = kc * 32;
        uint32_t asm_base = (uint32_t)__cvta_generic_to_shared(AsBase + buf * A_FLTS);
        uint32_t bsm_base = (uint32_t)__cvta_generic_to_shared(BsBase + buf * B_FLTS);
#pragma unroll
        for (int i = 0; i < 4; i++) {
            const int f   = tid + i * 256;
            const int row = f >> 3;
            const int c4  = (f & 7) * 4;
            cp16(asm_base + (row * 36 + c4) * 4,
                 A + (size_t)(bm + row) * Dc + k0 + c4);
        }
#pragma unroll
        for (int i = 0; i < 2; i++) {
            const int f   = tid + i * 256;
            const int row = f >> 3;
            const int c4  = (f & 7) * 4;
            cp16(bsm_base + (row * 36 + c4) * 4,
                 B + (size_t)(bn + row) * Dc + k0 + c4);
        }
        cp_commit();
    };

    copy_chunk(0, 0);

    for (int it = 0; it < NKC; it++) {
        const int cur = it & 1;
        if (it + 1 < NKC) {
            copy_chunk(it + 1, cur ^ 1);
            cp_wait<1>();
        } else {
            cp_wait<0>();
        }
        __syncthreads();

        const float* As = AsBase + cur * A_FLTS;
        const float* Bs = BsBase + cur * B_FLTS;
#pragma unroll
        for (int ks = 0; ks < 4; ks++) {
            uint32_t af[2][4], bf[4][2];
#pragma unroll
            for (int mt = 0; mt < 2; mt++) {
                const int r = wm * 32 + mt * 16 + g;
                af[mt][0] = __float_as_uint(As[(r    ) * 36 + ks * 8 + t    ]);
                af[mt][1] = __float_as_uint(As[(r + 8) * 36 + ks * 8 + t    ]);
                af[mt][2] = __float_as_uint(As[(r    ) * 36 + ks * 8 + t + 4]);
                af[mt][3] = __float_as_uint(As[(r + 8) * 36 + ks * 8 + t + 4]);
            }
#pragma unroll
            for (int nt = 0; nt < 4; nt++) {
                const int c = wn * 32 + nt * 8 + g;
                bf[nt][0] = __float_as_uint(Bs[c * 36 + ks * 8 + t    ]);
                bf[nt][1] = __float_as_uint(Bs[c * 36 + ks * 8 + t + 4]);
            }
#pragma unroll
            for (int mt = 0; mt < 2; mt++)
#pragma unroll
                for (int nt = 0; nt < 4; nt++)
                    mma_tf32(acc[mt][nt], af[mt], bf[nt]);
        }
        __syncthreads();
    }

#pragma unroll
    for (int mt = 0; mt < 2; mt++) {
#pragma unroll
        for (int nt = 0; nt < 4; nt++) {
            const int row = bm + wm * 32 + mt * 16 + g;
            const int col = bn + wn * 32 + nt * 8 + 2 * t;
            const float2 bv = *(const float2*)(bias + col);
            float2 o0, o1;
            o0.x = acc[mt][nt][0] + bv.x;
            o0.y = acc[mt][nt][1] + bv.y;
            o1.x = acc[mt][nt][2] + bv.x;
            o1.y = acc[mt][nt][3] + bv.y;
            if (roundOut) {
                o0.x = f2tf32f(o0.x);  o0.y = f2tf32f(o0.y);
                o1.x = f2tf32f(o1.x);  o1.y = f2tf32f(o1.y);
            }
            *(float2*)(C + (size_t)row * Dc + col)       = o0;
            *(float2*)(C + (size_t)(row + 8) * Dc + col) = o1;
        }
    }
}

// ---------------------------------------------------------------------------
// Flash attention v5: cp.async pipelined tiles.
//   K double-buffered (stride 68), V single-buffered (stride 72), dyn smem.
//   Steady state per tile kt (pending groups = {K[kt], V[kt]}):
//     wait<1> (K ready) -> sync -> issue cp K[kt+1] -> QK mma -> exp/Z/store
//     -> wait (V ready) -> sync -> PV mma -> sync -> issue cp V[kt+1].
//   Fills identical byte-streams to R11 (pre-rounded q/k/v) -> bit-identical.
// ---------------------------------------------------------------------------
constexpr int AT_Q = 64;     // q rows per block (4 warps x 16 rows)
constexpr int K_LD = 68;     // frag banks (4g+t) conflict-free
constexpr int V_LD = 72;     // frag banks (8t+g) conflict-free
constexpr int K_FLTS = 64 * K_LD;
constexpr int V_FLTS = 64 * V_LD;
constexpr int ATT_SMEM = (2 * K_FLTS + V_FLTS + AT_Q) * 4;   // 53504 B

__global__ __launch_bounds__(128, 4) void attention_flash5_kernel(float* __restrict__ attn)
{
    extern __shared__ float asmem[];
    float* Ks0   = asmem;
    float* Ks1   = Ks0 + K_FLTS;
    float* Vs    = Ks1 + K_FLTS;
    float* invZs = Vs + V_FLTS;

    const int tid  = threadIdx.x;
    const int lane = tid & 31;
    const int warp = tid >> 5;           // 0..3
    const int g    = lane >> 2;          // 0..7
    const int t    = lane & 3;           // 0..3

    const int qt = blockIdx.x;           // 0..31
    const int h  = blockIdx.y;
    const int b  = blockIdx.z;

    const float* Qg = g_q + (size_t)b * Sc * Dc + h * HDc;
    const float* Kg = g_k + (size_t)b * Sc * Dc + h * HDc;
    const float* Vg = g_v + (size_t)b * Sc * Dc + h * HDc;

    const int qrow = qt * AT_Q + warp * 16 + g;

    // ---- async fill helpers (8 cp16 per thread each) ----
    auto cp_K = [&](int kt, float* dst) {
        const uint32_t base = (uint32_t)__cvta_generic_to_shared(dst);
#pragma unroll
        for (int i = 0; i < 8; i++) {
            const int f  = tid + i * 128;
            const int r  = f >> 4;
            const int c4 = (f & 15) * 4;
            cp16(base + (r * K_LD + c4) * 4,
                 Kg + (size_t)(kt * 64 + r) * Dc + c4);
        }
        cp_commit();
    };
    auto cp_V = [&](int kt) {
        const uint32_t base = (uint32_t)__cvta_generic_to_shared(Vs);
#pragma unroll
        for (int i = 0; i < 8; i++) {
            const int f  = tid + i * 128;
            const int r  = f >> 4;
            const int c4 = (f & 15) * 4;
            cp16(base + (r * V_LD + c4) * 4,
                 Vg + (size_t)(kt * 64 + r) * Dc + c4);
        }
        cp_commit();
    };

    // ---- Q fragments: pre-rounded; x0.125 (2^-3) keeps tf32 exactness ----
    uint32_t qf[8][4];
#pragma unroll
    for (int ks = 0; ks < 8; ks++) {
        const float* q0 = Qg + (size_t)qrow * Dc + ks * 8;
        const float* q1 = Qg + (size_t)(qrow + 8) * Dc + ks * 8;
        qf[ks][0] = __float_as_uint(q0[t    ] * 0.125f);
        qf[ks][1] = __float_as_uint(q1[t    ] * 0.125f);
        qf[ks][2] = __float_as_uint(q0[t + 4] * 0.125f);
        qf[ks][3] = __float_as_uint(q1[t + 4] * 0.125f);
    }

    float ctx[8][4];
#pragma unroll
    for (int nt = 0; nt < 8; nt++)
#pragma unroll
        for (int i = 0; i < 4; i++) ctx[nt][i] = 0.f;

    float Z0 = 0.f, Z1 = 0.f;

    float* awr0 = attn + ((size_t)(b * Hc + h) * Sc + qrow) * Sc;
    float* awr1 = awr0 + (size_t)8 * Sc;

    // prologue: K0 then V0 in flight (commit order: K0, V0)
    cp_K(0, Ks0);
    cp_V(0);

    constexpr int NT = Sc / 64;   // 32 tiles
    for (int kt = 0; kt < NT; kt++) {
        float* Kcur = (kt & 1) ? Ks1 : Ks0;
        float* Knxt = (kt & 1) ? Ks0 : Ks1;

        // K[kt] ready (oldest pending group); V[kt] may still be in flight
        cp_wait<1>();
        __syncthreads();

        // prefetch next K into the spare buffer (its last reader finished
        // at tile kt-1's QK, behind the sync above)
        if (kt + 1 < NT) cp_K(kt + 1, Knxt);

        // ---- S = Q @ K^T ----
        float sacc[8][4];
#pragma unroll
        for (int nt = 0; nt < 8; nt++)
#pragma unroll
            for (int i = 0; i < 4; i++) sacc[nt][i] = 0.f;

#pragma unroll
        for (int ks = 0; ks < 8; ks++) {
#pragma unroll
            for (int nt = 0; nt < 8; nt++) {
                uint32_t bf[2];
                bf[0] = __float_as_uint(Kcur[(nt * 8 + g) * K_LD + ks * 8 + t    ]);
                bf[1] = __float_as_uint(Kcur[(nt * 8 + g) * K_LD + ks * 8 + t + 4]);
                mma_tf32(sacc[nt], qf[ks], bf);
            }
        }

        // ---- E = exp(S); Z partials; write E (V not needed yet) ----
#pragma unroll
        for (int nt = 0; nt < 8; nt++) {
            sacc[nt][0] = __expf(sacc[nt][0]);
            sacc[nt][1] = __expf(sacc[nt][1]);
            sacc[nt][2] = __expf(sacc[nt][2]);
            sacc[nt][3] = __expf(sacc[nt][3]);
            Z0 += sacc[nt][0] + sacc[nt][1];
            Z1 += sacc[nt][2] + sacc[nt][3];
            const int col = kt * 64 + nt * 8 + 2 * t;
            *(float2*)(awr0 + col) = make_float2(sacc[nt][0], sacc[nt][1]);
            *(float2*)(awr1 + col) = make_float2(sacc[nt][2], sacc[nt][3]);
        }

        // V[kt] ready (pending: {V[kt], K[kt+1]} -> leave K[kt+1] in flight)
        if (kt + 1 < NT) cp_wait<1>(); else cp_wait<0>();
        __syncthreads();

        // ---- ctx += E @ V (accumulator -> A fragment via shuffles, RNA) ----
        const int srcA = (lane & ~3) | (t >> 1);
        const bool odd = (t & 1);
#pragma unroll
        for (int j = 0; j < 8; j++) {
            const float e0 = __shfl_sync(0xffffffff, sacc[j][0], srcA);
            const float o0 = __shfl_sync(0xffffffff, sacc[j][1], srcA);
            const float e2 = __shfl_sync(0xffffffff, sacc[j][0], srcA + 2);
            const float o2 = __shfl_sync(0xffffffff, sacc[j][1], srcA + 2);
            const float e1 = __shfl_sync(0xffffffff, sacc[j][2], srcA);
            const float o1 = __shfl_sync(0xffffffff, sacc[j][3], srcA);
            const float e3 = __shfl_sync(0xffffffff, sacc[j][2], srcA + 2);
            const float o3 = __shfl_sync(0xffffffff, sacc[j][3], srcA + 2);
            uint32_t af[4];
            af[0] = f2tf32(odd ? o0 : e0);
            af[1] = f2tf32(odd ? o1 : e1);
            af[2] = f2tf32(odd ? o2 : e2);
            af[3] = f2tf32(odd ? o3 : e3);
#pragma unroll
            for (int nt = 0; nt < 8; nt++) {
                uint32_t bf[2];
                bf[0] = __float_as_uint(Vs[(j * 8 + t    ) * V_LD + nt * 8 + g]);
                bf[1] = __float_as_uint(Vs[(j * 8 + t + 4) * V_LD + nt * 8 + g]);
                mma_tf32(ctx[nt], af, bf);
            }
        }
        __syncthreads();   // all warps done reading Vs before refill

        if (kt + 1 < NT) cp_V(kt + 1);
    }

    // ---- reduce Z across t-lanes (once) ----
    Z0 += __shfl_xor_sync(0xffffffff, Z0, 1);
    Z0 += __shfl_xor_sync(0xffffffff, Z0, 2);
    Z1 += __shfl_xor_sync(0xffffffff, Z1, 1);
    Z1 += __shfl_xor_sync(0xffffffff, Z1, 2);
    const float invZ0 = 1.0f / Z0;
    const float invZ1 = 1.0f / Z1;

    // ---- write rounded normalized ctx ----
    float* c0 = g_ctx + (size_t)(b * Sc + qrow) * Dc + h * HDc;
    float* c1 = c0 + (size_t)8 * Dc;
#pragma unroll
    for (int nt = 0; nt < 8; nt++) {
        const int col = nt * 8 + 2 * t;
        *(float2*)(c0 + col) = make_float2(f2tf32f(ctx[nt][0] * invZ0),
                                           f2tf32f(ctx[nt][1] * invZ0));
        *(float2*)(c1 + col) = make_float2(f2tf32f(ctx[nt][2] * invZ1),
                                           f2tf32f(ctx[nt][3] * invZ1));
    }

    // ---- fused normalize: rescale own strip (warm in L2) ----
    if (t == 0) {
        invZs[warp * 16 + g]     = invZ0;
        invZs[warp * 16 + g + 8] = invZ1;
    }
    __syncthreads();

    float* strip = attn + ((size_t)(b * Hc + h) * Sc + (size_t)qt * AT_Q) * Sc;
    for (int r = 0; r < AT_Q; r++) {
        const float iz = invZs[r];
        float* rp = strip + (size_t)r * Sc;
#pragma unroll
        for (int i = 0; i < 4; i++) {
            const int c = (tid + i * 128) * 4;
            float4 v = *(const float4*)(rp + c);
            v.x *= iz;  v.y *= iz;  v.z *= iz;  v.w *= iz;
            *(float4*)(rp + c) = v;
        }
    }
}

// ---------------------------------------------------------------------------
// kernel_launch
//   d_in: x, Wq, bq, Wk, bk, Wv, bv, Wo, bo   (all fp32)
//   d_out: [ out (B*S*D) | attention_weights (B*H*S*S) ]  fp32
// ---------------------------------------------------------------------------
extern "C" void kernel_launch(void* const* d_in, const int* in_sizes, int n_in,
                              void* d_out, int out_size)
{
    (void)in_sizes; (void)n_in; (void)out_size;
    const float* x  = (const float*)d_in[0];
    const float* Wq = (const float*)d_in[1];
    const float* bq = (const float*)d_in[2];
    const float* Wk = (const float*)d_in[3];
    const float* bk = (const float*)d_in[4];
    const float* Wv = (const float*)d_in[5];
    const float* bv = (const float*)d_in[6];
    const float* Wo = (const float*)d_in[7];
    const float* bo = (const float*)d_in[8];

    float* out  = (float*)d_out;
    float* attn = out + (size_t)Bc * Sc * Dc;

    float* gq;  cudaGetSymbolAddress((void**)&gq,  g_q);
    float* gk;  cudaGetSymbolAddress((void**)&gk,  g_k);
    float* gv;  cudaGetSymbolAddress((void**)&gv,  g_v);
    float* gc;  cudaGetSymbolAddress((void**)&gc,  g_ctx);
    float* gxr; cudaGetSymbolAddress((void**)&gxr, g_xr);
    float* gwr; cudaGetSymbolAddress((void**)&gwr, g_wr);

    const float* wq = gwr;
    const float* wk = gwr + (size_t)Dc * Dc;
    const float* wv = gwr + 2 * (size_t)Dc * Dc;
    const float* wo = gwr + 3 * (size_t)Dc * Dc;

    // One-shot RNA rounding of x and all weights
    round_inputs<<<1024, 256>>>(x, Wq, Wk, Wv, Wo);

    cudaFuncSetAttribute(gemm3_cp, cudaFuncAttributeMaxDynamicSharedMemorySize, G_SMEM);
    cudaFuncSetAttribute(attention_flash5_kernel,
                         cudaFuncAttributeMaxDynamicSharedMemorySize, ATT_SMEM);

    dim3 gemmBlock(256);

    // Q/K/V projections (rounded outputs for the attention stage)
    dim3 qkvGrid(Dc / 64, Mc / 128, 3);      // (16, 32, 3)
    gemm3_cp<<<qkvGrid, gemmBlock, G_SMEM>>>(
        gxr, wq, bq, gq, wk, bk, gk, wv, bv, gv, 1);

    // Flash attention: weights (normalized in epilogue) + rounded ctx
    dim3 attnGrid(Sc / AT_Q, Hc, Bc);        // (32, 16, 2)
    attention_flash5_kernel<<<attnGrid, 128, ATT_SMEM>>>(attn);

    // Output projection (exact fp32 output)
    dim3 oGrid(Dc / 64, Mc / 128, 1);        // (16, 32, 1)
    gemm3_cp<<<oGrid, gemmBlock, G_SMEM>>>(
        gc, wo, bo, out, wo, bo, out, wo, bo, out, 0);
}

// round 13
// speedup vs baseline: 1.0360x; 1.0360x over previous
#include <cuda_runtime.h>
#include <math.h>
#include <stdint.h>

// Problem constants
constexpr int Bc  = 2;
constexpr int Sc  = 2048;
constexpr int Dc  = 1024;
constexpr int Hc  = 16;
constexpr int HDc = 64;
constexpr int Mc  = Bc * Sc;          // 4096 rows for projections

// ---------------------------------------------------------------------------
// Device scratch (allocations forbidden; use __device__ globals)
// ---------------------------------------------------------------------------
__device__ float g_q[(size_t)Bc * Sc * Dc];
__device__ float g_k[(size_t)Bc * Sc * Dc];
__device__ float g_v[(size_t)Bc * Sc * Dc];
__device__ float g_ctx[(size_t)Bc * Sc * Dc];
__device__ float g_xr[(size_t)Mc * Dc];         // rounded x
__device__ float g_wr[4][(size_t)Dc * Dc];      // rounded Wq, Wk, Wv, Wo

// ---------------------------------------------------------------------------
// Helpers
// ---------------------------------------------------------------------------
__device__ __forceinline__ uint32_t f2tf32(float f) {
    uint32_t u;
    asm("cvt.rna.tf32.f32 %0, %1;" : "=r"(u) : "f"(f));
    return u;
}
__device__ __forceinline__ float f2tf32f(float f) {
    return __uint_as_float(f2tf32(f));
}

// D += A(16x8, tf32) * B(8x8, tf32)   (m16n8k8, row.col)
__device__ __forceinline__ void mma_tf32(float* d, const uint32_t* a, const uint32_t* b) {
    asm volatile(
        "mma.sync.aligned.m16n8k8.row.col.f32.tf32.tf32.f32 "
        "{%0,%1,%2,%3}, {%4,%5,%6,%7}, {%8,%9}, {%0,%1,%2,%3};"
        : "+f"(d[0]), "+f"(d[1]), "+f"(d[2]), "+f"(d[3])
        : "r"(a[0]), "r"(a[1]), "r"(a[2]), "r"(a[3]), "r"(b[0]), "r"(b[1]));
}

__device__ __forceinline__ void cp16(uint32_t smem_dst, const void* gmem_src) {
    asm volatile("cp.async.cg.shared.global [%0], [%1], 16;"
                 :: "r"(smem_dst), "l"(gmem_src));
}
__device__ __forceinline__ void cp_commit() {
    asm volatile("cp.async.commit_group;");
}
template <int N>
__device__ __forceinline__ void cp_wait() {
    asm volatile("cp.async.wait_group %0;" :: "n"(N));
}

// ---------------------------------------------------------------------------
// One-shot RNA rounding of x and all four weight matrices.
// ---------------------------------------------------------------------------
__global__ __launch_bounds__(256) void round_inputs(
    const float* __restrict__ x,
    const float* __restrict__ Wq, const float* __restrict__ Wk,
    const float* __restrict__ Wv, const float* __restrict__ Wo)
{
    const size_t NX = (size_t)Mc * Dc / 4;
    const size_t NW = (size_t)Dc * Dc / 4;
    const size_t total = NX + 4 * NW;
    const size_t stride = (size_t)gridDim.x * blockDim.x;

    for (size_t i = (size_t)blockIdx.x * blockDim.x + threadIdx.x; i < total; i += stride) {
        const float4* src;
        float4* dst;
        if (i < NX) {
            src = (const float4*)x + i;
            dst = (float4*)g_xr + i;
        } else {
            const size_t j = i - NX;
            const int w = (int)(j / NW);
            const size_t o = j % NW;
            const float* ws = (w == 0) ? Wq : (w == 1) ? Wk : (w == 2) ? Wv : Wo;
            src = (const float4*)ws + o;
            dst = (float4*)g_wr[w] + o;
        }
        const float4 v = *src;
        *dst = make_float4(f2tf32f(v.x), f2tf32f(v.y), f2tf32f(v.z), f2tf32f(v.w));
    }
}

// ---------------------------------------------------------------------------
// tf32 GEMM v3 (NT), 3 problems via blockIdx.z, cp.async double-buffered.
// (unchanged from R11 — proven)
// ---------------------------------------------------------------------------
constexpr int NKC     = Dc / 32;                 // 32 k-chunks
constexpr int A_FLTS  = 128 * 36;                // one A buffer (floats)
constexpr int B_FLTS  = 64 * 36;
constexpr int G_SMEM  = 2 * (A_FLTS + B_FLTS) * 4;   // 55296 B

__global__ __launch_bounds__(256, 3) void gemm3_cp(
    const float* __restrict__ A,
    const float* __restrict__ W0, const float* __restrict__ b0, float* __restrict__ C0,
    const float* __restrict__ W1, const float* __restrict__ b1, float* __restrict__ C1,
    const float* __restrict__ W2, const float* __restrict__ b2, float* __restrict__ C2,
    int roundOut)
{
    const int z = blockIdx.z;
    const float* B    = (z == 0) ? W0 : (z == 1) ? W1 : W2;
    const float* bias = (z == 0) ? b0 : (z == 1) ? b1 : b2;
    float*       C    = (z == 0) ? C0 : (z == 1) ? C1 : C2;

    extern __shared__ float sm[];
    float* AsBase = sm;
    float* BsBase = sm + 2 * A_FLTS;

    const int tid  = threadIdx.x;
    const int lane = tid & 31;
    const int warp = tid >> 5;
    const int wm   = warp >> 1;
    const int wn   = warp & 1;
    const int g    = lane >> 2;
    const int t    = lane & 3;
    const int bm   = blockIdx.y * 128;
    const int bn   = blockIdx.x * 64;

    float acc[2][4][4];
#pragma unroll
    for (int mt = 0; mt < 2; mt++)
#pragma unroll
        for (int nt = 0; nt < 4; nt++)
#pragma unroll
            for (int i = 0; i < 4; i++) acc[mt][nt][i] = 0.f;

    auto copy_chunk = [&](int kc, int buf) {
        const int k0 = kc * 32;
        uint32_t asm_base = (uint32_t)__cvta_generic_to_shared(AsBase + buf * A_FLTS);
        uint32_t bsm_base = (uint32_t)__cvta_generic_to_shared(BsBase + buf * B_FLTS);
#pragma unroll
        for (int i = 0; i < 4; i++) {
            const int f   = tid + i * 256;
            const int row = f >> 3;
            const int c4  = (f & 7) * 4;
            cp16(asm_base + (row * 36 + c4) * 4,
                 A + (size_t)(bm + row) * Dc + k0 + c4);
        }
#pragma unroll
        for (int i = 0; i < 2; i++) {
            const int f   = tid + i * 256;
            const int row = f >> 3;
            const int c4  = (f & 7) * 4;
            cp16(bsm_base + (row * 36 + c4) * 4,
                 B + (size_t)(bn + row) * Dc + k0 + c4);
        }
        cp_commit();
    };

    copy_chunk(0, 0);

    for (int it = 0; it < NKC; it++) {
        const int cur = it & 1;
        if (it + 1 < NKC) {
            copy_chunk(it + 1, cur ^ 1);
            cp_wait<1>();
        } else {
            cp_wait<0>();
        }
        __syncthreads();

        const float* As = AsBase + cur * A_FLTS;
        const float* Bs = BsBase + cur * B_FLTS;
#pragma unroll
        for (int ks = 0; ks < 4; ks++) {
            uint32_t af[2][4], bf[4][2];
#pragma unroll
            for (int mt = 0; mt < 2; mt++) {
                const int r = wm * 32 + mt * 16 + g;
                af[mt][0] = __float_as_uint(As[(r    ) * 36 + ks * 8 + t    ]);
                af[mt][1] = __float_as_uint(As[(r + 8) * 36 + ks * 8 + t    ]);
                af[mt][2] = __float_as_uint(As[(r    ) * 36 + ks * 8 + t + 4]);
                af[mt][3] = __float_as_uint(As[(r + 8) * 36 + ks * 8 + t + 4]);
            }
#pragma unroll
            for (int nt = 0; nt < 4; nt++) {
                const int c = wn * 32 + nt * 8 + g;
                bf[nt][0] = __float_as_uint(Bs[c * 36 + ks * 8 + t    ]);
                bf[nt][1] = __float_as_uint(Bs[c * 36 + ks * 8 + t + 4]);
            }
#pragma unroll
            for (int mt = 0; mt < 2; mt++)
#pragma unroll
                for (int nt = 0; nt < 4; nt++)
                    mma_tf32(acc[mt][nt], af[mt], bf[nt]);
        }
        __syncthreads();
    }

#pragma unroll
    for (int mt = 0; mt < 2; mt++) {
#pragma unroll
        for (int nt = 0; nt < 4; nt++) {
            const int row = bm + wm * 32 + mt * 16 + g;
            const int col = bn + wn * 32 + nt * 8 + 2 * t;
            const float2 bv = *(const float2*)(bias + col);
            float2 o0, o1;
            o0.x = acc[mt][nt][0] + bv.x;
            o0.y = acc[mt][nt][1] + bv.y;
            o1.x = acc[mt][nt][2] + bv.x;
            o1.y = acc[mt][nt][3] + bv.y;
            if (roundOut) {
                o0.x = f2tf32f(o0.x);  o0.y = f2tf32f(o0.y);
                o1.x = f2tf32f(o1.x);  o1.y = f2tf32f(o1.y);
            }
            *(float2*)(C + (size_t)row * Dc + col)       = o0;
            *(float2*)(C + (size_t)(row + 8) * Dc + col) = o1;
        }
    }
}

// ---------------------------------------------------------------------------
// Flash attention v6: R11's flash4 body with AT_Q=128 (256 threads, 8 warps).
//   Each K/V tile now serves 128 q rows: per-thread fill halves and K/V L2
//   traffic halves. Per-warp math identical to R11 -> bit-identical results.
// ---------------------------------------------------------------------------
constexpr int AT_Q = 128;    // q rows per block (8 warps x 16 rows)
constexpr int K_LD = 68;     // frag banks (4g+t) conflict-free
constexpr int V_LD = 72;     // frag banks (8t+g) conflict-free

__global__ __launch_bounds__(256, 2) void attention_flash6_kernel(float* __restrict__ attn)
{
    __shared__ float Ks[64 * K_LD];
    __shared__ float Vs[64 * V_LD];
    __shared__ float invZs[AT_Q];

    const int tid  = threadIdx.x;
    const int lane = tid & 31;
    const int warp = tid >> 5;           // 0..7
    const int g    = lane >> 2;          // 0..7
    const int t    = lane & 3;           // 0..3

    const int qt = blockIdx.x;           // 0..15
    const int h  = blockIdx.y;
    const int b  = blockIdx.z;

    const float* Qg = g_q + (size_t)b * Sc * Dc + h * HDc;
    const float* Kg = g_k + (size_t)b * Sc * Dc + h * HDc;
    const float* Vg = g_v + (size_t)b * Sc * Dc + h * HDc;

    const int qrow = qt * AT_Q + warp * 16 + g;

    // ---- Q fragments: pre-rounded; x0.125 (2^-3) keeps tf32 exactness ----
    uint32_t qf[8][4];
#pragma unroll
    for (int ks = 0; ks < 8; ks++) {
        const float* q0 = Qg + (size_t)qrow * Dc + ks * 8;
        const float* q1 = Qg + (size_t)(qrow + 8) * Dc + ks * 8;
        qf[ks][0] = __float_as_uint(q0[t    ] * 0.125f);
        qf[ks][1] = __float_as_uint(q1[t    ] * 0.125f);
        qf[ks][2] = __float_as_uint(q0[t + 4] * 0.125f);
        qf[ks][3] = __float_as_uint(q1[t + 4] * 0.125f);
    }

    float ctx[8][4];
#pragma unroll
    for (int nt = 0; nt < 8; nt++)
#pragma unroll
        for (int i = 0; i < 4; i++) ctx[nt][i] = 0.f;

    float Z0 = 0.f, Z1 = 0.f;   // per-thread partials

    float* awr0 = attn + ((size_t)(b * Hc + h) * Sc + qrow) * Sc;
    float* awr1 = awr0 + (size_t)8 * Sc;

    for (int kt = 0; kt < Sc / 64; kt++) {
        // ---- load K and V tiles (coalesced float4), 4 slots per thread ----
#pragma unroll
        for (int i = 0; i < 4; i++) {
            const int f  = tid + i * 256;
            const int r  = f >> 4;
            const int c4 = (f & 15) * 4;
            *(float4*)(Ks + r * K_LD + c4) =
                *(const float4*)(Kg + (size_t)(kt * 64 + r) * Dc + c4);
            *(float4*)(Vs + r * V_LD + c4) =
                *(const float4*)(Vg + (size_t)(kt * 64 + r) * Dc + c4);
        }
        __syncthreads();

        // ---- S = Q @ K^T ----
        float sacc[8][4];
#pragma unroll
        for (int nt = 0; nt < 8; nt++)
#pragma unroll
            for (int i = 0; i < 4; i++) sacc[nt][i] = 0.f;

#pragma unroll
        for (int ks = 0; ks < 8; ks++) {
#pragma unroll
            for (int nt = 0; nt < 8; nt++) {
                uint32_t bf[2];
                bf[0] = __float_as_uint(Ks[(nt * 8 + g) * K_LD + ks * 8 + t    ]);
                bf[1] = __float_as_uint(Ks[(nt * 8 + g) * K_LD + ks * 8 + t + 4]);
                mma_tf32(sacc[nt], qf[ks], bf);
            }
        }

        // ---- E = exp(S); Z partials; write E straight from regs ----
#pragma unroll
        for (int nt = 0; nt < 8; nt++) {
            sacc[nt][0] = __expf(sacc[nt][0]);
            sacc[nt][1] = __expf(sacc[nt][1]);
            sacc[nt][2] = __expf(sacc[nt][2]);
            sacc[nt][3] = __expf(sacc[nt][3]);
            Z0 += sacc[nt][0] + sacc[nt][1];
            Z1 += sacc[nt][2] + sacc[nt][3];
            const int col = kt * 64 + nt * 8 + 2 * t;
            *(float2*)(awr0 + col) = make_float2(sacc[nt][0], sacc[nt][1]);
            *(float2*)(awr1 + col) = make_float2(sacc[nt][2], sacc[nt][3]);
        }

        // ---- ctx += E @ V (accumulator -> A fragment via shuffles, RNA) ----
        const int srcA = (lane & ~3) | (t >> 1);
        const bool odd = (t & 1);
#pragma unroll
        for (int j = 0; j < 8; j++) {
            const float e0 = __shfl_sync(0xffffffff, sacc[j][0], srcA);
            const float o0 = __shfl_sync(0xffffffff, sacc[j][1], srcA);
            const float e2 = __shfl_sync(0xffffffff, sacc[j][0], srcA + 2);
            const float o2 = __shfl_sync(0xffffffff, sacc[j][1], srcA + 2);
            const float e1 = __shfl_sync(0xffffffff, sacc[j][2], srcA);
            const float o1 = __shfl_sync(0xffffffff, sacc[j][3], srcA);
            const float e3 = __shfl_sync(0xffffffff, sacc[j][2], srcA + 2);
            const float o3 = __shfl_sync(0xffffffff, sacc[j][3], srcA + 2);
            uint32_t af[4];
            af[0] = f2tf32(odd ? o0 : e0);
            af[1] = f2tf32(odd ? o1 : e1);
            af[2] = f2tf32(odd ? o2 : e2);
            af[3] = f2tf32(odd ? o3 : e3);
#pragma unroll
            for (int nt = 0; nt < 8; nt++) {
                uint32_t bf[2];
                bf[0] = __float_as_uint(Vs[(j * 8 + t    ) * V_LD + nt * 8 + g]);
                bf[1] = __float_as_uint(Vs[(j * 8 + t + 4) * V_LD + nt * 8 + g]);
                mma_tf32(ctx[nt], af, bf);
            }
        }
        __syncthreads();   // before next tile overwrites Ks/Vs
    }

    // ---- reduce Z across t-lanes (once) ----
    Z0 += __shfl_xor_sync(0xffffffff, Z0, 1);
    Z0 += __shfl_xor_sync(0xffffffff, Z0, 2);
    Z1 += __shfl_xor_sync(0xffffffff, Z1, 1);
    Z1 += __shfl_xor_sync(0xffffffff, Z1, 2);
    const float invZ0 = 1.0f / Z0;
    const float invZ1 = 1.0f / Z1;

    // ---- write rounded normalized ctx ----
    float* c0 = g_ctx + (size_t)(b * Sc + qrow) * Dc + h * HDc;
    float* c1 = c0 + (size_t)8 * Dc;
#pragma unroll
    for (int nt = 0; nt < 8; nt++) {
        const int col = nt * 8 + 2 * t;
        *(float2*)(c0 + col) = make_float2(f2tf32f(ctx[nt][0] * invZ0),
                                           f2tf32f(ctx[nt][1] * invZ0));
        *(float2*)(c1 + col) = make_float2(f2tf32f(ctx[nt][2] * invZ1),
                                           f2tf32f(ctx[nt][3] * invZ1));
    }

    // ---- fused normalize: rescale own strip (warm in L2) ----
    if (t == 0) {
        invZs[warp * 16 + g]     = invZ0;
        invZs[warp * 16 + g + 8] = invZ1;
    }
    __syncthreads();

    float* strip = attn + ((size_t)(b * Hc + h) * Sc + (size_t)qt * AT_Q) * Sc;
    for (int r = 0; r < AT_Q; r++) {
        const float iz = invZs[r];
        float* rp = strip + (size_t)r * Sc;
#pragma unroll
        for (int i = 0; i < 2; i++) {
            const int c = (tid + i * 256) * 4;
            float4 v = *(const float4*)(rp + c);
            v.x *= iz;  v.y *= iz;  v.z *= iz;  v.w *= iz;
            *(float4*)(rp + c) = v;
        }
    }
}

// ---------------------------------------------------------------------------
// kernel_launch
//   d_in: x, Wq, bq, Wk, bk, Wv, bv, Wo, bo   (all fp32)
//   d_out: [ out (B*S*D) | attention_weights (B*H*S*S) ]  fp32
// ---------------------------------------------------------------------------
extern "C" void kernel_launch(void* const* d_in, const int* in_sizes, int n_in,
                              void* d_out, int out_size)
{
    (void)in_sizes; (void)n_in; (void)out_size;
    const float* x  = (const float*)d_in[0];
    const float* Wq = (const float*)d_in[1];
    const float* bq = (const float*)d_in[2];
    const float* Wk = (const float*)d_in[3];
    const float* bk = (const float*)d_in[4];
    const float* Wv = (const float*)d_in[5];
    const float* bv = (const float*)d_in[6];
    const float* Wo = (const float*)d_in[7];
    const float* bo = (const float*)d_in[8];

    float* out  = (float*)d_out;
    float* attn = out + (size_t)Bc * Sc * Dc;

    float* gq;  cudaGetSymbolAddress((void**)&gq,  g_q);
    float* gk;  cudaGetSymbolAddress((void**)&gk,  g_k);
    float* gv;  cudaGetSymbolAddress((void**)&gv,  g_v);
    float* gc;  cudaGetSymbolAddress((void**)&gc,  g_ctx);
    float* gxr; cudaGetSymbolAddress((void**)&gxr, g_xr);
    float* gwr; cudaGetSymbolAddress((void**)&gwr, g_wr);

    const float* wq = gwr;
    const float* wk = gwr + (size_t)Dc * Dc;
    const float* wv = gwr + 2 * (size_t)Dc * Dc;
    const float* wo = gwr + 3 * (size_t)Dc * Dc;

    // One-shot RNA rounding of x and all weights
    round_inputs<<<1024, 256>>>(x, Wq, Wk, Wv, Wo);

    cudaFuncSetAttribute(gemm3_cp, cudaFuncAttributeMaxDynamicSharedMemorySize, G_SMEM);

    dim3 gemmBlock(256);

    // Q/K/V projections (rounded outputs for the attention stage)
    dim3 qkvGrid(Dc / 64, Mc / 128, 3);      // (16, 32, 3)
    gemm3_cp<<<qkvGrid, gemmBlock, G_SMEM>>>(
        gxr, wq, bq, gq, wk, bk, gk, wv, bv, gv, 1);

    // Flash attention: weights (normalized in epilogue) + rounded ctx
    dim3 attnGrid(Sc / AT_Q, Hc, Bc);        // (16, 16, 2)
    attention_flash6_kernel<<<attnGrid, 256>>>(attn);

    // Output projection (exact fp32 output)
    dim3 oGrid(Dc / 64, Mc / 128, 1);        // (16, 32, 1)
    gemm3_cp<<<oGrid, gemmBlock, G_SMEM>>>(
        gc, wo, bo, out, wo, bo, out, wo, bo, out, 0);
}